// round 13
// baseline (speedup 1.0000x reference)
#include <cuda_runtime.h>
#include <cuda_bf16.h>

// Fixed problem shapes
#define IMG_H 544
#define IMG_W 960
#define OUT_H 136
#define OUT_W 240

// Each WARP produces a 30x8 output strip (120x32 mag region) by streaming
// 38 input rows with all intermediates in registers (no shared memory).
// 3-slot raw RGB register ring: consume row r+4, load row r+7 (distance 3).
// prefetch.global.L2 row r+10 at iter r => its LDG (iter r+3) hits L2.
#define TW 30

// Normalized 1D Gaussian, k=5, sigma=1.5
#define GW0 0.120078385f
#define GW1 0.233880757f
#define GW2 0.292081718f

__device__ __forceinline__ int reflect_idx(int i, int n) {
    if (i < 0) i = -i;
    if (i >= n) i = 2 * n - 2 - i;
    return i;
}

__device__ __forceinline__ float sqrt_approx(float x) {
    float r;
    asm("sqrt.approx.f32 %0, %1;" : "=f"(r) : "f"(x));
    return r;
}

__device__ __forceinline__ void pf_l2(const float* p) {
    asm volatile("prefetch.global.L2 [%0];" :: "l"(p));
}

__global__ __launch_bounds__(128, 4)
void EdgeGuidance_47313359733145_kernel(const float* __restrict__ in,
                                        float* __restrict__ out)
{
    const int lane = threadIdx.x & 31;
    const int wid  = threadIdx.x >> 5;
    const int ct   = blockIdx.x * 4 + wid;   // column tile 0..7 (30 out cols each)
    const int by   = blockIdx.y;             // row strip 0..16  (8 out rows each)
    const int b    = blockIdx.z;             // batch

    const int mx0 = ct * (TW * 4);           // mag-space x origin (120 per tile)
    const int my0 = by * 32;                 // mag-space y origin

    const float* __restrict__ pr = in + (size_t)b * 3 * IMG_H * IMG_W;
    const float* __restrict__ pg = pr + IMG_H * IMG_W;
    const float* __restrict__ pb = pg + IMG_H * IMG_W;

    // Lane's gray vec covers global x = gx0 .. gx0+3
    const int gx0 = mx0 - 4 + (lane << 2);
    const bool xfast = (gx0 >= 0) && (gx0 + 3 < IMG_W);
    const int rx0 = reflect_idx(gx0 + 0, IMG_W);
    const int rx1 = reflect_idx(gx0 + 1, IMG_W);
    const int rx2 = reflect_idx(gx0 + 2, IMG_W);
    const int rx3 = reflect_idx(gx0 + 3, IMG_W);

    // gs vec of this lane covers global x = gsx .. gsx+3
    const int gsx = mx0 - 1 + (lane << 2);
    const bool vx0 = (gsx + 0 >= 0) && (gsx + 0 < IMG_W);
    const bool vx1 = (gsx + 1 >= 0) && (gsx + 1 < IMG_W);
    const bool vx2 = (gsx + 2 < IMG_W);
    const bool vx3 = (gsx + 3 < IMG_W);

    const unsigned FULL = 0xffffffffu;

    // 3-slot raw RGB ring buffer
    float4 RB[3], GB[3], BB[3];

    // Issue loads for input row t into slot s. Global row = reflect(my0-3+t).
    auto loadraw = [&](int t, int s) {
        const int gy = reflect_idx(my0 - 3 + t, IMG_H);
        const int rowoff = gy * IMG_W;
        if (xfast) {
            RB[s] = *reinterpret_cast<const float4*>(pr + rowoff + gx0);
            GB[s] = *reinterpret_cast<const float4*>(pg + rowoff + gx0);
            BB[s] = *reinterpret_cast<const float4*>(pb + rowoff + gx0);
        } else {
            RB[s] = make_float4(pr[rowoff + rx0], pr[rowoff + rx1], pr[rowoff + rx2], pr[rowoff + rx3]);
            GB[s] = make_float4(pg[rowoff + rx0], pg[rowoff + rx1], pg[rowoff + rx2], pg[rowoff + rx3]);
            BB[s] = make_float4(pb[rowoff + rx0], pb[rowoff + rx1], pb[rowoff + rx2], pb[rowoff + rx3]);
        }
    };

    // L2 prefetch for input row t, all 3 planes (per-lane addresses cover the row).
    auto pfrow = [&](int t) {
        const int gy = reflect_idx(my0 - 3 + t, IMG_H);
        const int o = gy * IMG_W + rx0;
        pf_l2(pr + o);
        pf_l2(pg + o);
        pf_l2(pb + o);
    };

    // gray conversion + horizontal blur (shuffle-based) of slot s
    auto gb = [&](int s) -> float4 {
        const float4 r4 = RB[s], g4 = GB[s], b4 = BB[s];
        float4 A;
        A.x = fmaf(0.2989f, r4.x, fmaf(0.587f, g4.x, 0.114f * b4.x));
        A.y = fmaf(0.2989f, r4.y, fmaf(0.587f, g4.y, 0.114f * b4.y));
        A.z = fmaf(0.2989f, r4.z, fmaf(0.587f, g4.z, 0.114f * b4.z));
        A.w = fmaf(0.2989f, r4.w, fmaf(0.587f, g4.w, 0.114f * b4.w));

        const float Bx = __shfl_down_sync(FULL, A.x, 1);
        const float By = __shfl_down_sync(FULL, A.y, 1);
        const float Bz = __shfl_down_sync(FULL, A.z, 1);
        const float Bw = __shfl_down_sync(FULL, A.w, 1);
        const float C0 = __shfl_down_sync(FULL, A.x, 2);

        float4 o4;
        o4.x = fmaf(GW0, A.y, fmaf(GW1, A.z, fmaf(GW2, A.w, fmaf(GW1, Bx, GW0 * By))));
        o4.y = fmaf(GW0, A.z, fmaf(GW1, A.w, fmaf(GW2, Bx, fmaf(GW1, By, GW0 * Bz))));
        o4.z = fmaf(GW0, A.w, fmaf(GW1, Bx, fmaf(GW2, By, fmaf(GW1, Bz, GW0 * Bw))));
        o4.w = fmaf(GW0, Bx, fmaf(GW1, By, fmaf(GW2, Bz, fmaf(GW1, Bw, GW0 * C0))));
        return o4;
    };

    // Prologue: fill ring (rows 0..2), h-blur rows 0..3 while loading 3..6.
    // Prefetch rows 7..9 (their LDGs issue at iters 0..2).
    loadraw(0, 0); loadraw(1, 1); loadraw(2, 2);
    pfrow(7); pfrow(8); pfrow(9);
    float4 hb0 = gb(0); loadraw(3, 0);
    float4 hb1 = gb(1); loadraw(4, 1);
    float4 hb2 = gb(2); loadraw(5, 2);
    float4 hb3 = gb(0); loadraw(6, 0);
    // Invariant at iter r: raw(r+4) in slot (r+1)%3; raw(r+5), raw(r+6) in flight.

    float w0[6], w1[6], w2[6];
    float acc = 0.0f;

    const size_t outbase = ((size_t)b * OUT_H + by * 8) * OUT_W + ct * TW + lane;

    #pragma unroll
    for (int r = 0; r < 34; ++r) {
        if (r + 10 <= 37) pfrow(r + 10);     // L2 prefetch, LDG follows at iter r+3

        const int s = (r + 1) % 3;           // compile-time under full unroll
        const float4 h4 = gb(s);             // consume raw(r+4)
        if (r + 7 <= 37) loadraw(r + 7, s);  // refill slot (distance 3, hits L2)

        // Vertical Gaussian -> gs row r (global gy = my0-1+r)
        float4 g;
        g.x = fmaf(GW0, hb0.x, fmaf(GW1, hb1.x, fmaf(GW2, hb2.x, fmaf(GW1, hb3.x, GW0 * h4.x))));
        g.y = fmaf(GW0, hb0.y, fmaf(GW1, hb1.y, fmaf(GW2, hb2.y, fmaf(GW1, hb3.y, GW0 * h4.y))));
        g.z = fmaf(GW0, hb0.z, fmaf(GW1, hb1.z, fmaf(GW2, hb2.z, fmaf(GW1, hb3.z, GW0 * h4.z))));
        g.w = fmaf(GW0, hb0.w, fmaf(GW1, hb1.w, fmaf(GW2, hb2.w, fmaf(GW1, hb3.w, GW0 * h4.w))));

        const int gy = my0 - 1 + r;
        const bool yok = (gy >= 0) && (gy < IMG_H);
        g.x = (yok && vx0) ? g.x : 0.0f;
        g.y = (yok && vx1) ? g.y : 0.0f;
        g.z = (yok && vx2) ? g.z : 0.0f;
        g.w = (yok && vx3) ? g.w : 0.0f;

        w2[0] = g.x; w2[1] = g.y; w2[2] = g.z; w2[3] = g.w;
        w2[4] = __shfl_down_sync(FULL, g.x, 1);
        w2[5] = __shfl_down_sync(FULL, g.y, 1);

        if (r >= 2) {
            // Sobel + magnitude for mag row m = r-2 (uses gs rows r-2, r-1, r)
            float cv[6];
            #pragma unroll
            for (int c = 0; c < 6; c++) cv[c] = w0[c] + 2.0f * w1[c] + w2[c];

            #pragma unroll
            for (int c = 1; c <= 4; c++) {
                const float sgx = cv[c + 1] - cv[c - 1];
                const float sgy = (w2[c - 1] + 2.0f * w2[c] + w2[c + 1])
                                - (w0[c - 1] + 2.0f * w0[c] + w0[c + 1]);
                acc += sqrt_approx(fmaf(sgx, sgx, fmaf(sgy, sgy, 1e-6f)));
            }

            if (((r - 2) & 3) == 3) {        // r = 5, 9, ..., 33 -> 8 output rows
                const float down = acc * (1.0f / 16.0f);
                const float e = __expf(-5.0f * (down - 0.2f));
                const float sg = __fdividef(1.0f, 1.0f + e);
                if (lane < TW) {
                    out[outbase + (size_t)((r - 5) >> 2) * OUT_W] = sg * sg;
                }
                acc = 0.0f;
            }
        }

        // Shift windows (register renames under full unroll)
        hb0 = hb1; hb1 = hb2; hb2 = hb3; hb3 = h4;
        #pragma unroll
        for (int c = 0; c < 6; c++) { w0[c] = w1[c]; w1[c] = w2[c]; }
    }
}

extern "C" void kernel_launch(void* const* d_in, const int* in_sizes, int n_in,
                              void* d_out, int out_size)
{
    const float* in = (const float*)d_in[0];
    float* out = (float*)d_out;

    // 8 col tiles (4 warps per block) x 17 row strips x 16 batch
    dim3 grid(2, 17, 16);                    // 544 blocks of 128 threads
    EdgeGuidance_47313359733145_kernel<<<grid, 128>>>(in, out);
}

// round 14
// speedup vs baseline: 1.1460x; 1.1460x over previous
#include <cuda_runtime.h>
#include <cuda_bf16.h>

// Fixed problem shapes
#define IMG_H 544
#define IMG_W 960
#define OUT_H 136
#define OUT_W 240

// Each WARP (= one 32-thread block) produces a 30x8 output strip (120x32 mag
// region) by streaming 38 input rows with all intermediates in registers.
// 3-slot raw RGB register ring: consume row r+4, load row r+7 (distance 3).
// 1-warp blocks give fine-grained load balance: 2176 blocks / 148 SMs.
#define TW 30

// Normalized 1D Gaussian, k=5, sigma=1.5
#define GW0 0.120078385f
#define GW1 0.233880757f
#define GW2 0.292081718f

__device__ __forceinline__ int reflect_idx(int i, int n) {
    if (i < 0) i = -i;
    if (i >= n) i = 2 * n - 2 - i;
    return i;
}

__device__ __forceinline__ float sqrt_approx(float x) {
    float r;
    asm("sqrt.approx.f32 %0, %1;" : "=f"(r) : "f"(x));
    return r;
}

__global__ __launch_bounds__(32, 15)
void EdgeGuidance_47313359733145_kernel(const float* __restrict__ in,
                                        float* __restrict__ out)
{
    const int lane = threadIdx.x;            // 0..31
    const int ct   = blockIdx.x;             // column tile 0..7 (30 out cols each)
    const int by   = blockIdx.y;             // row strip 0..16  (8 out rows each)
    const int b    = blockIdx.z;             // batch

    const int mx0 = ct * (TW * 4);           // mag-space x origin (120 per tile)
    const int my0 = by * 32;                 // mag-space y origin

    const float* __restrict__ pr = in + (size_t)b * 3 * IMG_H * IMG_W;
    const float* __restrict__ pg = pr + IMG_H * IMG_W;
    const float* __restrict__ pb = pg + IMG_H * IMG_W;

    // Lane's gray vec covers global x = gx0 .. gx0+3
    const int gx0 = mx0 - 4 + (lane << 2);
    const bool xfast = (gx0 >= 0) && (gx0 + 3 < IMG_W);
    const int rx0 = reflect_idx(gx0 + 0, IMG_W);
    const int rx1 = reflect_idx(gx0 + 1, IMG_W);
    const int rx2 = reflect_idx(gx0 + 2, IMG_W);
    const int rx3 = reflect_idx(gx0 + 3, IMG_W);

    // gs vec of this lane covers global x = gsx .. gsx+3
    const int gsx = mx0 - 1 + (lane << 2);
    const bool vx0 = (gsx + 0 >= 0) && (gsx + 0 < IMG_W);
    const bool vx1 = (gsx + 1 >= 0) && (gsx + 1 < IMG_W);
    const bool vx2 = (gsx + 2 < IMG_W);
    const bool vx3 = (gsx + 3 < IMG_W);

    const unsigned FULL = 0xffffffffu;

    // 3-slot raw RGB ring buffer
    float4 RB[3], GB[3], BB[3];

    // Issue loads for input row t into slot s. Global row = reflect(my0-3+t).
    auto loadraw = [&](int t, int s) {
        const int gy = reflect_idx(my0 - 3 + t, IMG_H);
        const int rowoff = gy * IMG_W;
        if (xfast) {
            RB[s] = *reinterpret_cast<const float4*>(pr + rowoff + gx0);
            GB[s] = *reinterpret_cast<const float4*>(pg + rowoff + gx0);
            BB[s] = *reinterpret_cast<const float4*>(pb + rowoff + gx0);
        } else {
            RB[s] = make_float4(pr[rowoff + rx0], pr[rowoff + rx1], pr[rowoff + rx2], pr[rowoff + rx3]);
            GB[s] = make_float4(pg[rowoff + rx0], pg[rowoff + rx1], pg[rowoff + rx2], pg[rowoff + rx3]);
            BB[s] = make_float4(pb[rowoff + rx0], pb[rowoff + rx1], pb[rowoff + rx2], pb[rowoff + rx3]);
        }
    };

    // gray conversion + horizontal blur (shuffle-based) of slot s
    auto gb = [&](int s) -> float4 {
        const float4 r4 = RB[s], g4 = GB[s], b4 = BB[s];
        float4 A;
        A.x = fmaf(0.2989f, r4.x, fmaf(0.587f, g4.x, 0.114f * b4.x));
        A.y = fmaf(0.2989f, r4.y, fmaf(0.587f, g4.y, 0.114f * b4.y));
        A.z = fmaf(0.2989f, r4.z, fmaf(0.587f, g4.z, 0.114f * b4.z));
        A.w = fmaf(0.2989f, r4.w, fmaf(0.587f, g4.w, 0.114f * b4.w));

        const float Bx = __shfl_down_sync(FULL, A.x, 1);
        const float By = __shfl_down_sync(FULL, A.y, 1);
        const float Bz = __shfl_down_sync(FULL, A.z, 1);
        const float Bw = __shfl_down_sync(FULL, A.w, 1);
        const float C0 = __shfl_down_sync(FULL, A.x, 2);

        float4 o4;
        o4.x = fmaf(GW0, A.y, fmaf(GW1, A.z, fmaf(GW2, A.w, fmaf(GW1, Bx, GW0 * By))));
        o4.y = fmaf(GW0, A.z, fmaf(GW1, A.w, fmaf(GW2, Bx, fmaf(GW1, By, GW0 * Bz))));
        o4.z = fmaf(GW0, A.w, fmaf(GW1, Bx, fmaf(GW2, By, fmaf(GW1, Bz, GW0 * Bw))));
        o4.w = fmaf(GW0, Bx, fmaf(GW1, By, fmaf(GW2, Bz, fmaf(GW1, Bw, GW0 * C0))));
        return o4;
    };

    // Prologue: fill ring (rows 0..2), then h-blur rows 0..3 while loading 3..6.
    loadraw(0, 0); loadraw(1, 1); loadraw(2, 2);
    float4 hb0 = gb(0); loadraw(3, 0);
    float4 hb1 = gb(1); loadraw(4, 1);
    float4 hb2 = gb(2); loadraw(5, 2);
    float4 hb3 = gb(0); loadraw(6, 0);
    // Invariant at iter r: raw(r+4) in slot (r+1)%3; raw(r+5), raw(r+6) in flight.

    float w0[6], w1[6], w2[6];
    float acc = 0.0f;

    const size_t outbase = ((size_t)b * OUT_H + by * 8) * OUT_W + ct * TW + lane;

    #pragma unroll
    for (int r = 0; r < 34; ++r) {
        const int s = (r + 1) % 3;           // compile-time under full unroll
        const float4 h4 = gb(s);             // consume raw(r+4)
        if (r + 7 <= 37) loadraw(r + 7, s);  // refill slot (keeps depth 2-3)

        // Vertical Gaussian -> gs row r (global gy = my0-1+r)
        float4 g;
        g.x = fmaf(GW0, hb0.x, fmaf(GW1, hb1.x, fmaf(GW2, hb2.x, fmaf(GW1, hb3.x, GW0 * h4.x))));
        g.y = fmaf(GW0, hb0.y, fmaf(GW1, hb1.y, fmaf(GW2, hb2.y, fmaf(GW1, hb3.y, GW0 * h4.y))));
        g.z = fmaf(GW0, hb0.z, fmaf(GW1, hb1.z, fmaf(GW2, hb2.z, fmaf(GW1, hb3.z, GW0 * h4.z))));
        g.w = fmaf(GW0, hb0.w, fmaf(GW1, hb1.w, fmaf(GW2, hb2.w, fmaf(GW1, hb3.w, GW0 * h4.w))));

        const int gy = my0 - 1 + r;
        const bool yok = (gy >= 0) && (gy < IMG_H);
        g.x = (yok && vx0) ? g.x : 0.0f;
        g.y = (yok && vx1) ? g.y : 0.0f;
        g.z = (yok && vx2) ? g.z : 0.0f;
        g.w = (yok && vx3) ? g.w : 0.0f;

        w2[0] = g.x; w2[1] = g.y; w2[2] = g.z; w2[3] = g.w;
        w2[4] = __shfl_down_sync(FULL, g.x, 1);
        w2[5] = __shfl_down_sync(FULL, g.y, 1);

        if (r >= 2) {
            // Sobel + magnitude for mag row m = r-2 (uses gs rows r-2, r-1, r)
            float cv[6];
            #pragma unroll
            for (int c = 0; c < 6; c++) cv[c] = w0[c] + 2.0f * w1[c] + w2[c];

            #pragma unroll
            for (int c = 1; c <= 4; c++) {
                const float sgx = cv[c + 1] - cv[c - 1];
                const float sgy = (w2[c - 1] + 2.0f * w2[c] + w2[c + 1])
                                - (w0[c - 1] + 2.0f * w0[c] + w0[c + 1]);
                acc += sqrt_approx(fmaf(sgx, sgx, fmaf(sgy, sgy, 1e-6f)));
            }

            if (((r - 2) & 3) == 3) {        // r = 5, 9, ..., 33 -> 8 output rows
                const float down = acc * (1.0f / 16.0f);
                const float e = __expf(-5.0f * (down - 0.2f));
                const float sg = __fdividef(1.0f, 1.0f + e);
                if (lane < TW) {
                    out[outbase + (size_t)((r - 5) >> 2) * OUT_W] = sg * sg;
                }
                acc = 0.0f;
            }
        }

        // Shift windows (register renames under full unroll)
        hb0 = hb1; hb1 = hb2; hb2 = hb3; hb3 = h4;
        #pragma unroll
        for (int c = 0; c < 6; c++) { w0[c] = w1[c]; w1[c] = w2[c]; }
    }
}

extern "C" void kernel_launch(void* const* d_in, const int* in_sizes, int n_in,
                              void* d_out, int out_size)
{
    const float* in = (const float*)d_in[0];
    float* out = (float*)d_out;

    // 8 col tiles x 17 row strips x 16 batch, one warp per block
    dim3 grid(8, 17, 16);                    // 2176 blocks of 32 threads
    EdgeGuidance_47313359733145_kernel<<<grid, 32>>>(in, out);
}

// round 15
// speedup vs baseline: 1.3351x; 1.1649x over previous
#include <cuda_runtime.h>
#include <cuda_bf16.h>

// Fixed problem shapes
#define IMG_H 544
#define IMG_W 960
#define OUT_H 136
#define OUT_W 240

// Each WARP produces a 30x8 output strip (120x32 mag region) by streaming 38
// input rows with all intermediates in registers. PAIR-ITERATION version:
// 17 iterations, each handling TWO rows (load pair p+3, convert pair p+2,
// v-blur gs rows 2p/2p+1, sobel mag rows 2p-2/2p-1) for doubled ILP.
#define TW 30

// Normalized 1D Gaussian, k=5, sigma=1.5
#define GW0 0.120078385f
#define GW1 0.233880757f
#define GW2 0.292081718f

__device__ __forceinline__ int reflect_idx(int i, int n) {
    if (i < 0) i = -i;
    if (i >= n) i = 2 * n - 2 - i;
    return i;
}

__device__ __forceinline__ float sqrt_approx(float x) {
    float r;
    asm("sqrt.approx.f32 %0, %1;" : "=f"(r) : "f"(x));
    return r;
}

__global__ __launch_bounds__(64, 7)
void EdgeGuidance_47313359733145_kernel(const float* __restrict__ in,
                                        float* __restrict__ out)
{
    const int lane = threadIdx.x & 31;
    const int wid  = threadIdx.x >> 5;
    const int ct   = blockIdx.x * 2 + wid;   // column tile 0..7 (30 out cols)
    const int by   = blockIdx.y;             // row strip 0..16  (8 out rows)
    const int b    = blockIdx.z;             // batch

    const int mx0 = ct * (TW * 4);
    const int my0 = by * 32;

    const float* __restrict__ pr = in + (size_t)b * 3 * IMG_H * IMG_W;
    const float* __restrict__ pg = pr + IMG_H * IMG_W;
    const float* __restrict__ pb = pg + IMG_H * IMG_W;

    const int gx0 = mx0 - 4 + (lane << 2);
    const bool xfast = (gx0 >= 0) && (gx0 + 3 < IMG_W);
    const int rx0 = reflect_idx(gx0 + 0, IMG_W);
    const int rx1 = reflect_idx(gx0 + 1, IMG_W);
    const int rx2 = reflect_idx(gx0 + 2, IMG_W);
    const int rx3 = reflect_idx(gx0 + 3, IMG_W);

    const int gsx = mx0 - 1 + (lane << 2);
    const bool vx0 = (gsx + 0 >= 0) && (gsx + 0 < IMG_W);
    const bool vx1 = (gsx + 1 >= 0) && (gsx + 1 < IMG_W);
    const bool vx2 = (gsx + 2 < IMG_W);
    const bool vx3 = (gsx + 3 < IMG_W);

    const unsigned FULL = 0xffffffffu;

    // 2-slot PAIR ring: each slot holds 2 rows x 3 planes
    float4 RB[2][2], GB[2][2], BB[2][2];

    // Load one raw row t (global reflect(my0-3+t)) into slot s, sub-row j.
    auto loadrow = [&](int t, int s, int j) {
        const int gy = reflect_idx(my0 - 3 + t, IMG_H);
        const int rowoff = gy * IMG_W;
        if (xfast) {
            RB[s][j] = *reinterpret_cast<const float4*>(pr + rowoff + gx0);
            GB[s][j] = *reinterpret_cast<const float4*>(pg + rowoff + gx0);
            BB[s][j] = *reinterpret_cast<const float4*>(pb + rowoff + gx0);
        } else {
            RB[s][j] = make_float4(pr[rowoff + rx0], pr[rowoff + rx1], pr[rowoff + rx2], pr[rowoff + rx3]);
            GB[s][j] = make_float4(pg[rowoff + rx0], pg[rowoff + rx1], pg[rowoff + rx2], pg[rowoff + rx3]);
            BB[s][j] = make_float4(pb[rowoff + rx0], pb[rowoff + rx1], pb[rowoff + rx2], pb[rowoff + rx3]);
        }
    };
    // Load pair k (rows 2k, 2k+1) into slot s.
    auto loadpair = [&](int k, int s) {
        loadrow(2 * k, s, 0);
        loadrow(2 * k + 1, s, 1);
    };

    // gray + horizontal blur of slot s sub-row j
    auto gb = [&](int s, int j) -> float4 {
        const float4 r4 = RB[s][j], g4 = GB[s][j], b4 = BB[s][j];
        float4 A;
        A.x = fmaf(0.2989f, r4.x, fmaf(0.587f, g4.x, 0.114f * b4.x));
        A.y = fmaf(0.2989f, r4.y, fmaf(0.587f, g4.y, 0.114f * b4.y));
        A.z = fmaf(0.2989f, r4.z, fmaf(0.587f, g4.z, 0.114f * b4.z));
        A.w = fmaf(0.2989f, r4.w, fmaf(0.587f, g4.w, 0.114f * b4.w));

        const float Bx = __shfl_down_sync(FULL, A.x, 1);
        const float By = __shfl_down_sync(FULL, A.y, 1);
        const float Bz = __shfl_down_sync(FULL, A.z, 1);
        const float Bw = __shfl_down_sync(FULL, A.w, 1);
        const float C0 = __shfl_down_sync(FULL, A.x, 2);

        float4 o4;
        o4.x = fmaf(GW0, A.y, fmaf(GW1, A.z, fmaf(GW2, A.w, fmaf(GW1, Bx, GW0 * By))));
        o4.y = fmaf(GW0, A.z, fmaf(GW1, A.w, fmaf(GW2, Bx, fmaf(GW1, By, GW0 * Bz))));
        o4.z = fmaf(GW0, A.w, fmaf(GW1, Bx, fmaf(GW2, By, fmaf(GW1, Bz, GW0 * Bw))));
        o4.w = fmaf(GW0, Bx, fmaf(GW1, By, fmaf(GW2, Bz, fmaf(GW1, Bw, GW0 * C0))));
        return o4;
    };

    // Vertical 5-tap from hb window rows a..a+4 (passed explicitly)
    auto vg = [&](const float4& t0, const float4& t1, const float4& t2,
                  const float4& t3, const float4& t4, int r) -> float4 {
        float4 g;
        g.x = fmaf(GW0, t0.x, fmaf(GW1, t1.x, fmaf(GW2, t2.x, fmaf(GW1, t3.x, GW0 * t4.x))));
        g.y = fmaf(GW0, t0.y, fmaf(GW1, t1.y, fmaf(GW2, t2.y, fmaf(GW1, t3.y, GW0 * t4.y))));
        g.z = fmaf(GW0, t0.z, fmaf(GW1, t1.z, fmaf(GW2, t2.z, fmaf(GW1, t3.z, GW0 * t4.z))));
        g.w = fmaf(GW0, t0.w, fmaf(GW1, t1.w, fmaf(GW2, t2.w, fmaf(GW1, t3.w, GW0 * t4.w))));
        const int gy = my0 - 1 + r;
        const bool yok = (gy >= 0) && (gy < IMG_H);
        g.x = (yok && vx0) ? g.x : 0.0f;
        g.y = (yok && vx1) ? g.y : 0.0f;
        g.z = (yok && vx2) ? g.z : 0.0f;
        g.w = (yok && vx3) ? g.w : 0.0f;
        return g;
    };

    // Prologue: pairs 0,1 (rows 0..3) -> hb window; pair 2 -> ring slot 0.
    loadpair(0, 0);
    loadpair(1, 1);
    float4 hb0 = gb(0, 0);
    float4 hb1 = gb(0, 1);
    loadpair(2, 0);                          // slot 0 free after conversion
    float4 hb2 = gb(1, 0);
    float4 hb3 = gb(1, 1);
    // Invariant entering iter p: hb0..hb3 = rows 2p..2p+3; slot p&1 holds pair p+2.

    float w0[6], w1[6];                      // gs rows 2p-2, 2p-1
    float acc = 0.0f;

    const size_t outbase = ((size_t)b * OUT_H + by * 8) * OUT_W + ct * TW + lane;

    #pragma unroll
    for (int p = 0; p <= 16; ++p) {
        const int s = p & 1;
        // Load pair p+3 into the other slot (holds stale pair p+1)
        if (p + 3 <= 18) loadpair(p + 3, 1 - s);

        // Convert pair p+2 -> hb rows 2p+4, 2p+5 (two independent chains)
        const float4 hb4 = gb(s, 0);
        const float4 hb5 = gb(s, 1);

        // Vertical Gaussian -> gs rows 2p, 2p+1 (independent)
        const float4 g0 = vg(hb0, hb1, hb2, hb3, hb4, 2 * p);
        const float4 g1 = vg(hb1, hb2, hb3, hb4, hb5, 2 * p + 1);

        float w2[6], w3[6];
        w2[0] = g0.x; w2[1] = g0.y; w2[2] = g0.z; w2[3] = g0.w;
        w3[0] = g1.x; w3[1] = g1.y; w3[2] = g1.z; w3[3] = g1.w;
        w2[4] = __shfl_down_sync(FULL, g0.x, 1);
        w3[4] = __shfl_down_sync(FULL, g1.x, 1);
        w2[5] = __shfl_down_sync(FULL, g0.y, 1);
        w3[5] = __shfl_down_sync(FULL, g1.y, 1);

        if (p >= 1) {
            // Sobel + magnitude: mag rows 2p-2 (w0,w1,w2) and 2p-1 (w1,w2,w3)
            float cva[6], cvb[6];
            #pragma unroll
            for (int c = 0; c < 6; c++) {
                cva[c] = w0[c] + 2.0f * w1[c] + w2[c];
                cvb[c] = w1[c] + 2.0f * w2[c] + w3[c];
            }
            #pragma unroll
            for (int c = 1; c <= 4; c++) {
                const float ax = cva[c + 1] - cva[c - 1];
                const float ay = (w2[c - 1] + 2.0f * w2[c] + w2[c + 1])
                               - (w0[c - 1] + 2.0f * w0[c] + w0[c + 1]);
                const float bx = cvb[c + 1] - cvb[c - 1];
                const float by_ = (w3[c - 1] + 2.0f * w3[c] + w3[c + 1])
                                - (w1[c - 1] + 2.0f * w1[c] + w1[c + 1]);
                acc += sqrt_approx(fmaf(ax, ax, fmaf(ay, ay, 1e-6f)))
                     + sqrt_approx(fmaf(bx, bx, fmaf(by_, by_, 1e-6f)));
            }

            if ((p & 1) == 0) {              // p = 2,4,...,16: mag rows 4q..4q+3 done
                const float down = acc * (1.0f / 16.0f);
                const float e = __expf(-5.0f * (down - 0.2f));
                const float sg = __fdividef(1.0f, 1.0f + e);
                if (lane < TW) {
                    out[outbase + (size_t)(p / 2 - 1) * OUT_W] = sg * sg;
                }
                acc = 0.0f;
            }
        }

        // Shift windows (register renames under full unroll)
        hb0 = hb2; hb1 = hb3; hb2 = hb4; hb3 = hb5;
        #pragma unroll
        for (int c = 0; c < 6; c++) { w0[c] = w2[c]; w1[c] = w3[c]; }
    }
}

extern "C" void kernel_launch(void* const* d_in, const int* in_sizes, int n_in,
                              void* d_out, int out_size)
{
    const float* in = (const float*)d_in[0];
    float* out = (float*)d_out;

    // 8 col tiles (2 warps per block) x 17 row strips x 16 batch
    dim3 grid(4, 17, 16);                    // 1088 blocks of 64 threads
    EdgeGuidance_47313359733145_kernel<<<grid, 64>>>(in, out);
}